// round 4
// baseline (speedup 1.0000x reference)
#include <cuda_runtime.h>
#include <math.h>

#define BATCH   32768
#define NB      16
#define K       32
#define NSTATE  (NB*K)       // 256
#define IN_DIM  64
#define DT_C    0.05f
#define TAU_EPS 1e-6f
#define TPB     256

// Scratch (allocation-free rule: __device__ globals)
__device__ float g_buf0[BATCH*NSTATE];
__device__ float g_buf1[BATCH*NSTATE];
__device__ float g_T0[BATCH*K];   // E_l[0] @ net0  (constant across steps)
__device__ float g_a0[BATCH*K];   // |net0|         (constant across steps)

__device__ __forceinline__ float fast_tanh(float x) {
    float r;
    asm("tanh.approx.f32 %0, %1;" : "=f"(r) : "f"(x));
    return r;
}

// dot of a 32-wide smem row (16B aligned) with a register vector
__device__ __forceinline__ float dot32(const float* __restrict__ wrow, const float* v) {
    float acc = 0.f;
#pragma unroll
    for (int k4 = 0; k4 < 8; ++k4) {
        float4 w = reinterpret_cast<const float4*>(wrow)[k4];
        acc = fmaf(w.x, v[4*k4+0], acc);
        acc = fmaf(w.y, v[4*k4+1], acc);
        acc = fmaf(w.z, v[4*k4+2], acc);
        acc = fmaf(w.w, v[4*k4+3], acc);
    }
    return acc;
}

// ---------------- Kernel A: net0 precompute ----------------
// net0 = tanh(u_t @ W_in^T + b_in); store T0 = E_l[0] @ net0 and a0 = |net0|
__global__ __launch_bounds__(TPB) void ltcn_precompute(
    const float* __restrict__ u_t, const float* __restrict__ W_in,
    const float* __restrict__ b_in, const float* __restrict__ E_l)
{
    __shared__ __align__(16) float sWin[K*IN_DIM];
    __shared__ __align__(16) float sEl0[K*K];
    __shared__ float sbin[K];
    int tid = threadIdx.x;
    for (int i = tid; i < K*IN_DIM; i += TPB) sWin[i] = W_in[i];
    for (int i = tid; i < K*K;     i += TPB) sEl0[i] = E_l[i];
    if (tid < K) sbin[tid] = b_in[tid];
    __syncthreads();

    int b = blockIdx.x * TPB + tid;
    if (b >= BATCH) return;

    float u[IN_DIM];
    const float4* up = reinterpret_cast<const float4*>(u_t + (size_t)b * IN_DIM);
#pragma unroll
    for (int i = 0; i < IN_DIM/4; ++i) {
        float4 t = up[i];
        u[4*i+0] = t.x; u[4*i+1] = t.y; u[4*i+2] = t.z; u[4*i+3] = t.w;
    }

    float n0[K];
#pragma unroll 4
    for (int l = 0; l < K; ++l) {
        float acc = sbin[l];
        const float* wr = sWin + l * IN_DIM;
#pragma unroll
        for (int i4 = 0; i4 < IN_DIM/4; ++i4) {
            float4 w = reinterpret_cast<const float4*>(wr)[i4];
            acc = fmaf(w.x, u[4*i4+0], acc);
            acc = fmaf(w.y, u[4*i4+1], acc);
            acc = fmaf(w.z, u[4*i4+2], acc);
            acc = fmaf(w.w, u[4*i4+3], acc);
        }
        n0[l] = fast_tanh(acc);
    }

    float t0[K], a0[K];
#pragma unroll 4
    for (int l = 0; l < K; ++l) {
        t0[l] = dot32(sEl0 + l*K, n0);
        a0[l] = fabsf(n0[l]);
    }
    float4* t0p = reinterpret_cast<float4*>(g_T0 + (size_t)b * K);
    float4* a0p = reinterpret_cast<float4*>(g_a0 + (size_t)b * K);
#pragma unroll
    for (int i = 0; i < 8; ++i) {
        t0p[i] = make_float4(t0[4*i], t0[4*i+1], t0[4*i+2], t0[4*i+3]);
        a0p[i] = make_float4(a0[4*i], a0[4*i+1], a0[4*i+2], a0[4*i+3]);
    }
}

// ---------------- Step kernel ----------------
// grid.x = batch tiles, grid.y = block index j. One thread = one batch element
// of one block; weights for block j staged in smem (warp-broadcast reads).
__global__ __launch_bounds__(TPB) void ltcn_step(
    const float* __restrict__ src, float* __restrict__ dst,
    const float* __restrict__ W_fwd, const float* __restrict__ b_fwd,
    const float* __restrict__ W_rec, const float* __restrict__ b_rec,
    const float* __restrict__ E_l,   const float* __restrict__ E_lr,
    const float* __restrict__ tau_raw, const int* __restrict__ n_steps, int s)
{
    __shared__ __align__(16) float sWf[K*K];
    __shared__ __align__(16) float sWr[K*K];
    __shared__ __align__(16) float sEl[K*K];
    __shared__ __align__(16) float sElr[K*K];
    __shared__ float sbf[K], sbr[K], sit[K];

    int tid = threadIdx.x;
    int j = blockIdx.y;

    for (int i = tid; i < K*K; i += TPB) {
        sWr[i]  = W_rec[j*K*K + i];
        sEl[i]  = E_l  [j*K*K + i];
        sElr[i] = E_lr [j*K*K + i];
        if (j > 0) sWf[i] = W_fwd[(j-1)*K*K + i];
    }
    if (tid < K) {
        sbr[tid] = b_rec[j*K + tid];
        sbf[tid] = (j > 0) ? b_fwd[(j-1)*K + tid] : 0.f;
        float t  = tau_raw[j*K + tid];
        float sp = (t > 20.f) ? t : log1pf(expf(t));   // softplus
        sit[tid] = 1.0f / (sp + TAU_EPS);
    }
    __syncthreads();

    size_t b = (size_t)blockIdx.x * TPB + tid;
    if (b >= BATCH) return;
    const float* yin  = src + b * NSTATE + (size_t)j * K;
    float*       yout = dst + b * NSTATE + (size_t)j * K;

    if (s >= *n_steps) {   // passthrough when beyond requested steps
#pragma unroll
        for (int i = 0; i < 8; ++i)
            reinterpret_cast<float4*>(yout)[i] = reinterpret_cast<const float4*>(yin)[i];
        return;
    }

    float y[K];
#pragma unroll
    for (int i = 0; i < 8; ++i) {
        float4 t = reinterpret_cast<const float4*>(yin)[i];
        y[4*i+0] = t.x; y[4*i+1] = t.y; y[4*i+2] = t.z; y[4*i+3] = t.w;
    }

    // net_rec = tanh(W_rec[j] @ y + b_rec[j])
    float nr[K];
#pragma unroll 4
    for (int l = 0; l < K; ++l)
        nr[l] = fast_tanh(dot32(sWr + l*K, y) + sbr[l]);

    if (j == 0) {
        float t0[K], a0[K];
        const float4* t0p = reinterpret_cast<const float4*>(g_T0 + b * K);
        const float4* a0p = reinterpret_cast<const float4*>(g_a0 + b * K);
#pragma unroll
        for (int i = 0; i < 8; ++i) {
            float4 t = t0p[i]; t0[4*i]=t.x; t0[4*i+1]=t.y; t0[4*i+2]=t.z; t0[4*i+3]=t.w;
            float4 a = a0p[i]; a0[4*i]=a.x; a0[4*i+1]=a.y; a0[4*i+2]=a.z; a0[4*i+3]=a.w;
        }
#pragma unroll 4
        for (int l = 0; l < K; ++l) {
            float o = t0[l] + dot32(sElr + l*K, nr);
            float d = sit[l] + a0[l] + fabsf(nr[l]);
            y[l] = fmaf(DT_C, o - y[l]*d, y[l]);
        }
    } else {
        // net_out = tanh(W_fwd[j-1] @ y_{j-1} + b_fwd[j-1]) from step-start snapshot
        float yp[K];
        const float4* ypp = reinterpret_cast<const float4*>(src + b * NSTATE + (size_t)(j-1) * K);
#pragma unroll
        for (int i = 0; i < 8; ++i) {
            float4 t = ypp[i];
            yp[4*i+0] = t.x; yp[4*i+1] = t.y; yp[4*i+2] = t.z; yp[4*i+3] = t.w;
        }
        float no[K];
#pragma unroll 4
        for (int l = 0; l < K; ++l)
            no[l] = fast_tanh(dot32(sWf + l*K, yp) + sbf[l]);
#pragma unroll 4
        for (int l = 0; l < K; ++l) {
            float o = dot32(sEl + l*K, no) + dot32(sElr + l*K, nr);
            float d = sit[l] + fabsf(no[l]) + fabsf(nr[l]);
            y[l] = fmaf(DT_C, o - y[l]*d, y[l]);
        }
    }

#pragma unroll
    for (int i = 0; i < 8; ++i)
        reinterpret_cast<float4*>(yout)[i] =
            make_float4(y[4*i], y[4*i+1], y[4*i+2], y[4*i+3]);
}

extern "C" void kernel_launch(void* const* d_in, const int* in_sizes, int n_in,
                              void* d_out, int out_size)
{
    const float* y     = (const float*)d_in[0];
    const float* u_t   = (const float*)d_in[1];
    const float* W_in  = (const float*)d_in[2];
    const float* b_in  = (const float*)d_in[3];
    const float* W_fwd = (const float*)d_in[4];
    const float* b_fwd = (const float*)d_in[5];
    const float* W_rec = (const float*)d_in[6];
    const float* b_rec = (const float*)d_in[7];
    const float* E_l   = (const float*)d_in[8];
    const float* E_lr  = (const float*)d_in[9];
    const float* tau   = (const float*)d_in[10];
    const int*   nst   = (const int*)d_in[11];
    float* out = (float*)d_out;

    float *buf0, *buf1;
    cudaGetSymbolAddress((void**)&buf0, g_buf0);
    cudaGetSymbolAddress((void**)&buf1, g_buf1);

    ltcn_precompute<<<BATCH/TPB, TPB>>>(u_t, W_in, b_in, E_l);

    dim3 grid(BATCH/TPB, NB);
    for (int s = 0; s < 8; ++s) {
        const float* srcp = (s == 0) ? y   : ((s & 1) ? buf0 : buf1);
        float*       dstp = (s == 7) ? out : ((s & 1) ? buf1 : buf0);
        ltcn_step<<<grid, TPB>>>(srcp, dstp, W_fwd, b_fwd, W_rec, b_rec,
                                 E_l, E_lr, tau, nst, s);
    }
}

// round 5
// speedup vs baseline: 1.2418x; 1.2418x over previous
#include <cuda_runtime.h>
#include <math.h>

#define BATCH   32768
#define NB      16
#define K       32
#define NSTATE  (NB*K)       // 256
#define IN_DIM  64
#define DT_C    0.05f
#define TAU_EPS 1e-6f
#define TPB     256

typedef unsigned long long u64t;

// Scratch (allocation-free rule: __device__ globals)
__device__ float g_buf0[BATCH*NSTATE];
__device__ float g_buf1[BATCH*NSTATE];
__device__ float g_T0[BATCH*K];   // E_l[0] @ net0  (constant across steps)
__device__ float g_a0[BATCH*K];   // |net0|         (constant across steps)

// E_l (all 16 blocks) in constant memory, stored as packed f32x2 pairs. 64KB.
__constant__ __align__(16) u64t c_El[NB*K*K/2];

__device__ __forceinline__ float fast_tanh(float x) {
    float r;
    asm("tanh.approx.f32 %0, %1;" : "=f"(r) : "f"(x));
    return r;
}

// ---- packed f32x2 helpers ----
__device__ __forceinline__ u64t pack2(float lo, float hi) {
    u64t d; asm("mov.b64 %0, {%1, %2};" : "=l"(d) : "f"(lo), "f"(hi)); return d;
}
__device__ __forceinline__ void unpack2(float& lo, float& hi, u64t v) {
    asm("mov.b64 {%0, %1}, %2;" : "=f"(lo), "=f"(hi) : "l"(v));
}
__device__ __forceinline__ u64t fma2(u64t a, u64t b, u64t c) {
    u64t d; asm("fma.rn.f32x2 %0, %1, %2, %3;" : "=l"(d) : "l"(a), "l"(b), "l"(c)); return d;
}
__device__ __forceinline__ u64t add2(u64t a, u64t b) {
    u64t d; asm("add.rn.f32x2 %0, %1, %2;" : "=l"(d) : "l"(a), "l"(b)); return d;
}

// packed dot: 32-wide smem row (16B aligned) vs 16-pack register vector; + bias
__device__ __forceinline__ float dot32p(const float* __restrict__ wrow,
                                        const u64t* v, float bias) {
    u64t a0 = pack2(bias, 0.f);
    u64t a1 = 0ULL;
    const ulonglong2* w2 = reinterpret_cast<const ulonglong2*>(wrow);
#pragma unroll
    for (int i = 0; i < 8; ++i) {
        ulonglong2 w = w2[i];
        a0 = fma2(w.x, v[2*i+0], a0);
        a1 = fma2(w.y, v[2*i+1], a1);
    }
    a0 = add2(a0, a1);
    float lo, hi; unpack2(lo, hi, a0);
    return lo + hi;
}

// dual packed dot: c_El[cbase..] . va  +  smem row wb . vb
__device__ __forceinline__ float dot32p2c(int cbase, const u64t* va,
                                          const float* __restrict__ wb, const u64t* vb) {
    u64t a0 = 0ULL, a1 = 0ULL;
#pragma unroll
    for (int i = 0; i < 8; ++i) {
        ulonglong2 wa = *reinterpret_cast<const ulonglong2*>(&c_El[cbase + 2*i]);
        a0 = fma2(wa.x, va[2*i+0], a0);
        a1 = fma2(wa.y, va[2*i+1], a1);
    }
    const ulonglong2* w2 = reinterpret_cast<const ulonglong2*>(wb);
#pragma unroll
    for (int i = 0; i < 8; ++i) {
        ulonglong2 w = w2[i];
        a0 = fma2(w.x, vb[2*i+0], a0);
        a1 = fma2(w.y, vb[2*i+1], a1);
    }
    a0 = add2(a0, a1);
    float lo, hi; unpack2(lo, hi, a0);
    return lo + hi;
}

// load 32 floats (16B aligned) into 16 packed regs
__device__ __forceinline__ void load_packed(u64t* dst, const float* __restrict__ p) {
    const ulonglong2* p2 = reinterpret_cast<const ulonglong2*>(p);
#pragma unroll
    for (int i = 0; i < 8; ++i) { ulonglong2 t = p2[i]; dst[2*i] = t.x; dst[2*i+1] = t.y; }
}
__device__ __forceinline__ void store_packed(float* __restrict__ p, const u64t* src) {
    ulonglong2* p2 = reinterpret_cast<ulonglong2*>(p);
#pragma unroll
    for (int i = 0; i < 8; ++i) { ulonglong2 t; t.x = src[2*i]; t.y = src[2*i+1]; p2[i] = t; }
}

// ---------------- Kernel A: net0 precompute ----------------
__global__ __launch_bounds__(TPB) void ltcn_precompute(
    const float* __restrict__ u_t, const float* __restrict__ W_in,
    const float* __restrict__ b_in, const float* __restrict__ E_l)
{
    __shared__ __align__(16) float sWin[K*IN_DIM];
    __shared__ __align__(16) float sEl0[K*K];
    __shared__ float sbin[K];
    int tid = threadIdx.x;
    for (int i = tid; i < K*IN_DIM; i += TPB) sWin[i] = W_in[i];
    for (int i = tid; i < K*K;     i += TPB) sEl0[i] = E_l[i];
    if (tid < K) sbin[tid] = b_in[tid];
    __syncthreads();

    int b = blockIdx.x * TPB + tid;
    if (b >= BATCH) return;

    u64t u[32];
    load_packed(u,      u_t + (size_t)b * IN_DIM);
    load_packed(u + 16, u_t + (size_t)b * IN_DIM + 32);

    float n0s[K];
#pragma unroll 4
    for (int l = 0; l < K; ++l) {
        const float* wr = sWin + l * IN_DIM;
        u64t a0 = pack2(sbin[l], 0.f), a1 = 0ULL;
        const ulonglong2* w2 = reinterpret_cast<const ulonglong2*>(wr);
#pragma unroll
        for (int i = 0; i < 16; ++i) {
            ulonglong2 w = w2[i];
            a0 = fma2(w.x, u[2*i+0], a0);
            a1 = fma2(w.y, u[2*i+1], a1);
        }
        a0 = add2(a0, a1);
        float lo, hi; unpack2(lo, hi, a0);
        n0s[l] = fast_tanh(lo + hi);
    }

    u64t n0[16];
#pragma unroll
    for (int i = 0; i < 16; ++i) n0[i] = pack2(n0s[2*i], n0s[2*i+1]);

    float t0[K], a0v[K];
#pragma unroll 4
    for (int l = 0; l < K; ++l) {
        t0[l]  = dot32p(sEl0 + l*K, n0, 0.f);
        a0v[l] = fabsf(n0s[l]);
    }
    float4* t0p = reinterpret_cast<float4*>(g_T0 + (size_t)b * K);
    float4* a0p = reinterpret_cast<float4*>(g_a0 + (size_t)b * K);
#pragma unroll
    for (int i = 0; i < 8; ++i) {
        t0p[i] = make_float4(t0[4*i],  t0[4*i+1],  t0[4*i+2],  t0[4*i+3]);
        a0p[i] = make_float4(a0v[4*i], a0v[4*i+1], a0v[4*i+2], a0v[4*i+3]);
    }
}

// ---------------- Step kernel ----------------
__global__ __launch_bounds__(TPB, 2) void ltcn_step(
    const float* __restrict__ src, float* __restrict__ dst,
    const float* __restrict__ W_fwd, const float* __restrict__ b_fwd,
    const float* __restrict__ W_rec, const float* __restrict__ b_rec,
    const float* __restrict__ E_lr,
    const float* __restrict__ tau_raw, const int* __restrict__ n_steps, int s)
{
    __shared__ __align__(16) float sWf[K*K];
    __shared__ __align__(16) float sWr[K*K];
    __shared__ __align__(16) float sElr[K*K];
    __shared__ float sbf[K], sbr[K], sit[K];

    int tid = threadIdx.x;
    int j = blockIdx.y;

    for (int i = tid; i < K*K; i += TPB) {
        sWr[i]  = W_rec[j*K*K + i];
        sElr[i] = E_lr [j*K*K + i];
        if (j > 0) sWf[i] = W_fwd[(j-1)*K*K + i];
    }
    if (tid < K) {
        sbr[tid] = b_rec[j*K + tid];
        sbf[tid] = (j > 0) ? b_fwd[(j-1)*K + tid] : 0.f;
        float t  = tau_raw[j*K + tid];
        float sp = (t > 20.f) ? t : log1pf(expf(t));   // softplus
        sit[tid] = 1.0f / (sp + TAU_EPS);
    }
    __syncthreads();

    size_t b = (size_t)blockIdx.x * TPB + tid;
    if (b >= BATCH) return;
    const float* yin  = src + b * NSTATE + (size_t)j * K;
    float*       yout = dst + b * NSTATE + (size_t)j * K;

    if (s >= *n_steps) {   // passthrough beyond requested steps
        u64t tmp[16];
        load_packed(tmp, yin);
        store_packed(yout, tmp);
        return;
    }

    u64t y[16];
    load_packed(y, yin);

    // net_rec = tanh(W_rec[j] @ y + b_rec[j]), packed
    u64t nrp[16];
#pragma unroll
    for (int i = 0; i < 16; ++i) {
        float lo = fast_tanh(dot32p(sWr + (2*i+0)*K, y, sbr[2*i+0]));
        float hi = fast_tanh(dot32p(sWr + (2*i+1)*K, y, sbr[2*i+1]));
        nrp[i] = pack2(lo, hi);
    }

    if (j == 0) {
        u64t t0p[16], a0p[16];
        load_packed(t0p, g_T0 + b * K);
        load_packed(a0p, g_a0 + b * K);
#pragma unroll
        for (int i = 0; i < 16; ++i) {
            float t0lo, t0hi; unpack2(t0lo, t0hi, t0p[i]);
            float a0lo, a0hi; unpack2(a0lo, a0hi, a0p[i]);
            float olo = dot32p(sElr + (2*i+0)*K, nrp, t0lo);
            float ohi = dot32p(sElr + (2*i+1)*K, nrp, t0hi);
            float nrlo, nrhi; unpack2(nrlo, nrhi, nrp[i]);
            float ylo, yhi;   unpack2(ylo, yhi, y[i]);
            float dlo = sit[2*i+0] + a0lo + fabsf(nrlo);
            float dhi = sit[2*i+1] + a0hi + fabsf(nrhi);
            ylo = fmaf(DT_C, olo - ylo*dlo, ylo);
            yhi = fmaf(DT_C, ohi - yhi*dhi, yhi);
            y[i] = pack2(ylo, yhi);
        }
    } else {
        // net_out = tanh(W_fwd[j-1] @ y_{j-1} + b_fwd[j-1]) from step-start snapshot
        u64t yp[16];
        load_packed(yp, src + b * NSTATE + (size_t)(j-1) * K);
        u64t nop[16];
#pragma unroll
        for (int i = 0; i < 16; ++i) {
            float lo = fast_tanh(dot32p(sWf + (2*i+0)*K, yp, sbf[2*i+0]));
            float hi = fast_tanh(dot32p(sWf + (2*i+1)*K, yp, sbf[2*i+1]));
            nop[i] = pack2(lo, hi);
        }
        const int elbase = j * (K*K/2);
#pragma unroll
        for (int i = 0; i < 16; ++i) {
            float olo = dot32p2c(elbase + (2*i+0)*(K/2), nop, sElr + (2*i+0)*K, nrp);
            float ohi = dot32p2c(elbase + (2*i+1)*(K/2), nop, sElr + (2*i+1)*K, nrp);
            float nolo, nohi; unpack2(nolo, nohi, nop[i]);
            float nrlo, nrhi; unpack2(nrlo, nrhi, nrp[i]);
            float ylo, yhi;   unpack2(ylo, yhi, y[i]);
            float dlo = sit[2*i+0] + fabsf(nolo) + fabsf(nrlo);
            float dhi = sit[2*i+1] + fabsf(nohi) + fabsf(nrhi);
            ylo = fmaf(DT_C, olo - ylo*dlo, ylo);
            yhi = fmaf(DT_C, ohi - yhi*dhi, yhi);
            y[i] = pack2(ylo, yhi);
        }
    }

    store_packed(yout, y);
}

extern "C" void kernel_launch(void* const* d_in, const int* in_sizes, int n_in,
                              void* d_out, int out_size)
{
    const float* y     = (const float*)d_in[0];
    const float* u_t   = (const float*)d_in[1];
    const float* W_in  = (const float*)d_in[2];
    const float* b_in  = (const float*)d_in[3];
    const float* W_fwd = (const float*)d_in[4];
    const float* b_fwd = (const float*)d_in[5];
    const float* W_rec = (const float*)d_in[6];
    const float* b_rec = (const float*)d_in[7];
    const float* E_l   = (const float*)d_in[8];
    const float* E_lr  = (const float*)d_in[9];
    const float* tau   = (const float*)d_in[10];
    const int*   nst   = (const int*)d_in[11];
    float* out = (float*)d_out;

    float *buf0, *buf1;
    cudaGetSymbolAddress((void**)&buf0, g_buf0);
    cudaGetSymbolAddress((void**)&buf1, g_buf1);

    // E_l -> constant memory (same bytes; viewed as packed f32x2 pairs)
    cudaMemcpyToSymbolAsync(c_El, E_l, NB*K*K*sizeof(float), 0,
                            cudaMemcpyDeviceToDevice, 0);

    ltcn_precompute<<<BATCH/TPB, TPB>>>(u_t, W_in, b_in, E_l);

    dim3 grid(BATCH/TPB, NB);
    for (int s = 0; s < 8; ++s) {
        const float* srcp = (s == 0) ? y   : ((s & 1) ? buf0 : buf1);
        float*       dstp = (s == 7) ? out : ((s & 1) ? buf1 : buf0);
        ltcn_step<<<grid, TPB>>>(srcp, dstp, W_fwd, b_fwd, W_rec, b_rec,
                                 E_lr, tau, nst, s);
    }
}